// round 10
// baseline (speedup 1.0000x reference)
#include <cuda_runtime.h>
#include <math.h>
#include <stdint.h>

#define Bb 8
#define Qn 128
#define Kn 256
#define Dd 512
#define Hh 512
#define Vv 512
#define HUGEF 1000000000.0f
#define RSQRT 0.04419417382415922f   // 1/sqrt(512)

// Scratch (allocation-free rule: __device__ globals)
__device__ float g_qproj[Bb*Qn*Hh];   // 2 MB
__device__ float g_kproj[Bb*Kn*Hh];   // 4 MB (compacted rows, b1 folded in)
__device__ float g_scores[Bb*Qn*Kn];  // 1 MB (only unmasked cols written)
__device__ int   g_kidx[Bb*Kn];       // compacted unmasked k indices (64-padded)
__device__ int   g_kcnt[Bb];

typedef unsigned long long u64;
__device__ __forceinline__ u64 pack2(float x, float y){
    u64 r; asm("mov.b64 %0, {%1,%2};" : "=l"(r) : "f"(x), "f"(y)); return r;
}
__device__ __forceinline__ void fma2(u64& d, u64 a, u64 b){
    asm("fma.rn.f32x2 %0, %1, %2, %0;" : "+l"(d) : "l"(a), "l"(b));
}
__device__ __forceinline__ void unpack2(u64 v, float& lo, float& hi){
    asm("mov.b64 {%0,%1}, %2;" : "=f"(lo), "=f"(hi) : "l"(v));
}
__device__ __forceinline__ float fast_tanh(float x){
    float r; asm("tanh.approx.f32 %0, %1;" : "=f"(r) : "f"(x)); return r;
}
__device__ __forceinline__ uint32_t f2tf(float x){
    uint32_t r; asm("cvt.rna.tf32.f32 %0, %1;" : "=r"(r) : "f"(x)); return r;
}
__device__ __forceinline__ void mma_tf32(float* d, const uint32_t* a, const uint32_t* b){
    asm volatile("mma.sync.aligned.m16n8k8.row.col.f32.tf32.tf32.f32 "
        "{%0,%1,%2,%3}, {%4,%5,%6,%7}, {%8,%9}, {%0,%1,%2,%3};"
        : "+f"(d[0]), "+f"(d[1]), "+f"(d[2]), "+f"(d[3])
        : "r"(a[0]), "r"(a[1]), "r"(a[2]), "r"(a[3]), "r"(b[0]), "r"(b[1]));
}

// ---------------------------------------------------------------------------
// Kernel 0: per-batch compaction of unmasked k (64-padded with first index).
// ---------------------------------------------------------------------------
__global__ __launch_bounds__(256) void compact_kernel(const int* __restrict__ mask){
    int b = blockIdx.x, t = threadIdx.x;
    int lane = t & 31, w = t >> 5;
    int keep = (mask[b*Kn + t] == 0);
    unsigned bal = __ballot_sync(0xffffffffu, keep);
    int rank = __popc(bal & ((1u << lane) - 1u));
    __shared__ int wcnt[8];
    if (lane == 0) wcnt[w] = __popc(bal);
    __syncthreads();
    int off = 0, total = 0;
    #pragma unroll
    for (int i = 0; i < 8; i++){ if (i < w) off += wcnt[i]; total += wcnt[i]; }
    if (keep) g_kidx[b*Kn + off + rank] = t;
    __syncthreads();
    int cntp = (total + 63) & ~63;
    int first = (total > 0) ? g_kidx[b*Kn] : 0;
    for (int i = total + t; i < cntp; i += 256) g_kidx[b*Kn + i] = first;
    if (t == 0) g_kcnt[b] = total;
}

// ---------------------------------------------------------------------------
// Kernel 1: projections via tf32 mma.sync (m16n8k8). Block = 64 rows x 64
// cols, 8 warps (2m x 4n), warp tile 32x16, k-chunk 32 double-buffered,
// operands tf32-converted at staging. Row tiles 0..15 = query; 16..47 =
// compacted key rows (b1 folded in epilogue).
// ---------------------------------------------------------------------------
__global__ __launch_bounds__(256) void projmma_kernel(const float* __restrict__ query,
                                                      const float* __restrict__ key,
                                                      const float* __restrict__ W1,
                                                      const float* __restrict__ b1){
    __shared__ uint32_t As[2][64][36];   // [buf][row][k]  (4r+k)%32 conflict-free
    __shared__ uint32_t Bs[2][32][72];   // [buf][k][n]    (8k+n)%32 conflict-free
    int tid = threadIdx.x;
    int wid = tid >> 5, lane = tid & 31;
    int lane4 = lane & 3, laneg = lane >> 2;
    int colTile = blockIdx.x * 64;
    int tile = blockIdx.y;
    bool isQ = tile < (Bb*Qn/64);        // 16 q-tiles
    int b = 0, pos0 = 0;

    // staging indices
    int row_a = tid >> 2;                // 0..63
    int kc8   = (tid & 3) * 8;           // 0,8,16,24
    int kb    = tid >> 3;                // 0..31
    int nc8   = (tid & 7) * 8;           // 0..56

    const float* Arow;
    if (isQ){
        Arow = query + (size_t)(tile*64 + row_a)*Dd;
    } else {
        int t = tile - (Bb*Qn/64);       // 0..31
        b = t >> 2; pos0 = (t & 3) * 64;
        int cntp = (g_kcnt[b] + 63) & ~63;
        if (pos0 >= cntp) return;
        Arow = key + ((size_t)b*Kn + g_kidx[b*Kn + pos0 + row_a])*Dd;
    }
    const float* Wbase = W1 + (size_t)(isQ ? 0 : Dd)*Hh + colTile;

    int warp_m = wid >> 2;               // 0..1
    int warp_n = wid & 3;                // 0..3
    int rm = warp_m * 32;
    int cn = warp_n * 16;

    float d[2][2][4];
    #pragma unroll
    for (int t = 0; t < 2; t++)
        #pragma unroll
        for (int u = 0; u < 2; u++)
            #pragma unroll
            for (int r = 0; r < 4; r++) d[t][u][r] = 0.0f;

    // prefetch chunk 0
    float4 av0 = *(const float4*)(Arow + kc8);
    float4 av1 = *(const float4*)(Arow + kc8 + 4);
    float4 bv0 = *(const float4*)(Wbase + (size_t)kb*Hh + nc8);
    float4 bv1 = *(const float4*)(Wbase + (size_t)kb*Hh + nc8 + 4);

    const int NCH = Dd/32;
    for (int ch = 0; ch < NCH; ch++){
        int cur = ch & 1;
        // store with tf32 conversion
        {
            uint4 u0 = make_uint4(f2tf(av0.x), f2tf(av0.y), f2tf(av0.z), f2tf(av0.w));
            uint4 u1 = make_uint4(f2tf(av1.x), f2tf(av1.y), f2tf(av1.z), f2tf(av1.w));
            *(uint4*)&As[cur][row_a][kc8]     = u0;
            *(uint4*)&As[cur][row_a][kc8 + 4] = u1;
            uint4 w0 = make_uint4(f2tf(bv0.x), f2tf(bv0.y), f2tf(bv0.z), f2tf(bv0.w));
            uint4 w1 = make_uint4(f2tf(bv1.x), f2tf(bv1.y), f2tf(bv1.z), f2tf(bv1.w));
            *(uint4*)&Bs[cur][kb][nc8]     = w0;
            *(uint4*)&Bs[cur][kb][nc8 + 4] = w1;
        }
        __syncthreads();
        if (ch + 1 < NCH){
            int k0 = (ch + 1) * 32;
            av0 = *(const float4*)(Arow + k0 + kc8);
            av1 = *(const float4*)(Arow + k0 + kc8 + 4);
            bv0 = *(const float4*)(Wbase + (size_t)(k0 + kb)*Hh + nc8);
            bv1 = *(const float4*)(Wbase + (size_t)(k0 + kb)*Hh + nc8 + 4);
        }
        #pragma unroll
        for (int s = 0; s < 4; s++){
            int k0s = s * 8;
            uint32_t afr[2][4], bfr[2][2];
            #pragma unroll
            for (int t = 0; t < 2; t++){
                int r = rm + t*16 + laneg;
                afr[t][0] = As[cur][r  ][k0s + lane4];
                afr[t][1] = As[cur][r+8][k0s + lane4];
                afr[t][2] = As[cur][r  ][k0s + lane4 + 4];
                afr[t][3] = As[cur][r+8][k0s + lane4 + 4];
            }
            #pragma unroll
            for (int u = 0; u < 2; u++){
                int c = cn + u*8 + laneg;
                bfr[u][0] = Bs[cur][k0s + lane4    ][c];
                bfr[u][1] = Bs[cur][k0s + lane4 + 4][c];
            }
            mma_tf32(d[0][0], afr[0], bfr[0]);
            mma_tf32(d[0][1], afr[0], bfr[1]);
            mma_tf32(d[1][0], afr[1], bfr[0]);
            mma_tf32(d[1][1], afr[1], bfr[1]);
        }
    }

    // epilogue: D layout c0,c1 -> (row, 2*lane4 + {0,1}); c2,c3 -> row+8
    #pragma unroll
    for (int t = 0; t < 2; t++){
        #pragma unroll
        for (int u = 0; u < 2; u++){
            int colOff = cn + u*8 + 2*lane4;
            float bx = 0.0f, by = 0.0f;
            if (!isQ){
                float2 bb = *(const float2*)(b1 + colTile + colOff);
                bx = bb.x; by = bb.y;
            }
            int rlocal = rm + t*16 + laneg;
            float* outp;
            if (isQ) outp = g_qproj + ((size_t)(tile*64) + rlocal)*Hh + colTile + colOff;
            else     outp = g_kproj + ((size_t)(b*Kn + pos0) + rlocal)*Hh + colTile + colOff;
            *(float2*)outp = make_float2(d[t][u][0] + bx, d[t][u][1] + by);
            *(float2*)(outp + 8*Hh) = make_float2(d[t][u][2] + bx, d[t][u][3] + by);
        }
    }
}

// ---------------------------------------------------------------------------
// Kernel 2: scores over compacted k. 16q x 32k per block, double-buffered.
// ---------------------------------------------------------------------------
__global__ __launch_bounds__(256) void score_kernel(const float* __restrict__ w2){
    int b  = blockIdx.z;
    int cnt = g_kcnt[b];
    int cntp = (cnt + 63) & ~63;
    int k0 = blockIdx.x * 32;
    if (k0 >= cntp) return;
    int q0 = blockIdx.y * 16;
    __shared__ float qs[2][32][17];
    __shared__ float ks[2][32][34];
    __shared__ float wsm[2][32];
    __shared__ int sidx[32];
    int tid = threadIdx.x;
    if (tid < 32) sidx[tid] = g_kidx[b*Kn + k0 + tid];
    int tx = tid & 15;
    int ty = tid >> 4;
    const float* qbase = g_qproj + (size_t)(b*Qn + q0)*Hh;
    const float* kbase = g_kproj + ((size_t)b*Kn + k0)*Hh;

    float acc0 = 0.0f, acc1 = 0.0f;
    int qr = tid >> 3, qc4 = (tid & 7) * 4;
    int kr = tid >> 3, kc4 = (tid & 7) * 4;

    float4 qv4 = make_float4(0,0,0,0), kv4;
    float wv0 = 0.0f;
    if (tid < 128) qv4 = *(const float4*)(qbase + (size_t)qr*Hh + qc4);
    kv4 = *(const float4*)(kbase + (size_t)kr*Hh + kc4);
    if (tid < 32) wv0 = w2[tid];

    const int NCH = Hh/32;
    for (int ch = 0; ch < NCH; ch++){
        int cur = ch & 1;
        if (tid < 128){
            qs[cur][qc4+0][qr] = qv4.x; qs[cur][qc4+1][qr] = qv4.y;
            qs[cur][qc4+2][qr] = qv4.z; qs[cur][qc4+3][qr] = qv4.w;
        }
        ks[cur][kc4+0][kr] = kv4.x; ks[cur][kc4+1][kr] = kv4.y;
        ks[cur][kc4+2][kr] = kv4.z; ks[cur][kc4+3][kr] = kv4.w;
        if (tid < 32) wsm[cur][tid] = wv0;
        __syncthreads();
        if (ch + 1 < NCH){
            int h0 = (ch + 1) * 32;
            if (tid < 128) qv4 = *(const float4*)(qbase + (size_t)qr*Hh + h0 + qc4);
            kv4 = *(const float4*)(kbase + (size_t)kr*Hh + h0 + kc4);
            if (tid < 32) wv0 = w2[h0 + tid];
        }
        #pragma unroll
        for (int h = 0; h < 32; h++){
            float wv = wsm[cur][h];
            float qv = qs[cur][h][ty];
            float2 kv = *(const float2*)&ks[cur][h][tx*2];
            acc0 += wv * fast_tanh(qv + kv.x);
            acc1 += wv * fast_tanh(qv + kv.y);
        }
    }
    int qq = b*Qn + q0 + ty;
    g_scores[(size_t)qq*Kn + sidx[tx*2+0]] = acc0 * RSQRT;
    g_scores[(size_t)qq*Kn + sidx[tx*2+1]] = acc1 * RSQRT;
}

// ---------------------------------------------------------------------------
// Kernel 3: row softmax; masked cols substituted in-register (exp -> 0).
// ---------------------------------------------------------------------------
__global__ __launch_bounds__(256) void softmax_kernel(const int* __restrict__ mask,
                                                      float* __restrict__ out_w){
    int row = blockIdx.x;
    int b = row >> 7;
    int t = threadIdx.x;
    int lane = t & 31, warp = t >> 5;
    __shared__ float red[8];
    float s = (mask[b*Kn + t] != 0) ? (-HUGEF * RSQRT)
                                    : g_scores[(size_t)row*Kn + t];
    float m = s;
    #pragma unroll
    for (int o = 16; o > 0; o >>= 1) m = fmaxf(m, __shfl_xor_sync(0xffffffffu, m, o));
    if (lane == 0) red[warp] = m;
    __syncthreads();
    float m8 = red[0];
    #pragma unroll
    for (int i = 1; i < 8; i++) m8 = fmaxf(m8, red[i]);
    float e = __expf(s - m8);
    float sum = e;
    #pragma unroll
    for (int o = 16; o > 0; o >>= 1) sum += __shfl_xor_sync(0xffffffffu, sum, o);
    __syncthreads();
    if (lane == 0) red[warp] = sum;
    __syncthreads();
    float s8 = 0.0f;
    #pragma unroll
    for (int i = 0; i < 8; i++) s8 += red[i];
    out_w[(size_t)row*Kn + t] = e / s8;
}

// ---------------------------------------------------------------------------
// Kernel 4: attn_vec GEMM over compacted k, f32x2, double-buffered.
// ---------------------------------------------------------------------------
__global__ __launch_bounds__(256) void attnvec_kernel(const float* __restrict__ value,
                                                      const float* __restrict__ attn_w,
                                                      float* __restrict__ out_v){
    __shared__ float ws[2][16][33];
    __shared__ float vs[2][16][68];
    __shared__ int sidx[Kn];
    int b  = blockIdx.z;
    int q0 = blockIdx.y * 32;
    int v0 = blockIdx.x * 64;
    int tid = threadIdx.x;
    int tx = tid & 15, ty = tid >> 4;
    int cnt = g_kcnt[b];
    bool useidx = (cnt > 0);
    int n  = useidx ? cnt : Kn;
    int np = (n + 15) & ~15;
    for (int i = tid; i < np; i += 256) sidx[i] = useidx ? g_kidx[b*Kn + i] : i;
    __syncthreads();

    int wq = tid >> 3, wk2 = (tid & 7) * 2;
    int vk = tid >> 4, vc4 = (tid & 15) * 4;
    const float* wrow  = attn_w + (size_t)(b*Qn + q0 + wq)*Kn;
    const float* vbase = value + (size_t)b*Kn*Vv + v0 + vc4;

    u64 acc2[2][2];
    acc2[0][0]=0ull; acc2[0][1]=0ull; acc2[1][0]=0ull; acc2[1][1]=0ull;

    float wr0, wr1; float4 vv;
    wr0 = (wk2+0 < n) ? wrow[sidx[wk2+0]] : 0.0f;
    wr1 = (wk2+1 < n) ? wrow[sidx[wk2+1]] : 0.0f;
    vv = *(const float4*)(vbase + (size_t)sidx[vk]*Vv);

    int nch = np / 16;
    for (int ch = 0; ch < nch; ch++){
        int cur = ch & 1;
        ws[cur][wk2+0][wq] = wr0;
        ws[cur][wk2+1][wq] = wr1;
        *(float4*)&vs[cur][vk][vc4] = vv;
        __syncthreads();
        if (ch + 1 < nch){
            int k0 = (ch + 1) * 16;
            wr0 = (k0+wk2+0 < n) ? wrow[sidx[k0+wk2+0]] : 0.0f;
            wr1 = (k0+wk2+1 < n) ? wrow[sidx[k0+wk2+1]] : 0.0f;
            vv = *(const float4*)(vbase + (size_t)sidx[k0+vk]*Vv);
        }
        #pragma unroll
        for (int kk = 0; kk < 16; kk++){
            float a0 = ws[cur][kk][ty*2+0];
            float a1 = ws[cur][kk][ty*2+1];
            ulonglong2 cv = *(const ulonglong2*)&vs[cur][kk][tx*4];
            u64 ad;
            ad = pack2(a0,a0); fma2(acc2[0][0],ad,cv.x); fma2(acc2[0][1],ad,cv.y);
            ad = pack2(a1,a1); fma2(acc2[1][0],ad,cv.x); fma2(acc2[1][1],ad,cv.y);
        }
    }

    float* outp = out_v + (size_t)(b*Qn + q0)*Vv + v0;
    #pragma unroll
    for (int i = 0; i < 2; i++){
        float o0,o1,o2,o3;
        unpack2(acc2[i][0],o0,o1); unpack2(acc2[i][1],o2,o3);
        *(float4*)(outp + (size_t)(ty*2+i)*Vv + tx*4) = make_float4(o0,o1,o2,o3);
    }
}

// ---------------------------------------------------------------------------
extern "C" void kernel_launch(void* const* d_in, const int* in_sizes, int n_in,
                              void* d_out, int out_size){
    const float* query = (const float*)d_in[0];
    const float* key_  = (const float*)d_in[1];
    const float* value = (const float*)d_in[2];
    const int*   mask  = (const int*)  d_in[3];
    const float* W1    = (const float*)d_in[4];
    const float* b1    = (const float*)d_in[5];
    const float* w2    = (const float*)d_in[6];

    float* out = (float*)d_out;
    float* out_vec = out;                       // (B,Q,V)
    float* out_w   = out + (size_t)Bb*Qn*Vv;    // (B,Q,K)

    compact_kernel<<<Bb, 256>>>(mask);

    dim3 gp(Hh/64, (Bb*Qn + Bb*Kn)/64);         // (8, 48); key tiles may exit
    projmma_kernel<<<gp, 256>>>(query, key_, W1, b1);

    dim3 g2(Kn/32, Qn/16, Bb);                  // (8, 8, 8); ~half exit
    score_kernel<<<g2, 256>>>(w2);

    softmax_kernel<<<Bb*Qn, 256>>>(mask, out_w);

    dim3 g4(Vv/64, Qn/32, Bb);                  // (8, 4, 8)
    attnvec_kernel<<<g4, 256>>>(value, out_w, out_vec);
}

// round 12
// speedup vs baseline: 1.1373x; 1.1373x over previous
#include <cuda_runtime.h>
#include <math.h>
#include <stdint.h>

#define Bb 8
#define Qn 128
#define Kn 256
#define Dd 512
#define Hh 512
#define Vv 512
#define HUGEF 1000000000.0f
#define RSQRT 0.04419417382415922f   // 1/sqrt(512)

// Scratch (allocation-free rule: __device__ globals)
__device__ float g_qproj[Bb*Qn*Hh];   // 2 MB
__device__ float g_kproj[Bb*Kn*Hh];   // 4 MB (compacted rows, b1 folded in)
__device__ float g_scores[Bb*Qn*Kn];  // 1 MB (only unmasked cols written)

typedef unsigned long long u64;
__device__ __forceinline__ u64 pack2(float x, float y){
    u64 r; asm("mov.b64 %0, {%1,%2};" : "=l"(r) : "f"(x), "f"(y)); return r;
}
__device__ __forceinline__ void fma2(u64& d, u64 a, u64 b){
    asm("fma.rn.f32x2 %0, %1, %2, %0;" : "+l"(d) : "l"(a), "l"(b));
}
__device__ __forceinline__ void unpack2(u64 v, float& lo, float& hi){
    asm("mov.b64 {%0,%1}, %2;" : "=f"(lo), "=f"(hi) : "l"(v));
}
__device__ __forceinline__ float fast_tanh(float x){
    float r; asm("tanh.approx.f32 %0, %1;" : "=f"(r) : "f"(x)); return r;
}

// ---------------------------------------------------------------------------
// In-block compaction: 256 threads cooperatively build the compacted index
// list for batch b into sidx[] (padded to `pad` with the first index), and
// return the true count. Replaces the separate compact kernel (saves one
// launch + graph dependency). ~500 cyc; mask is 1KB, L2-resident.
// Requires blockDim.x == 256. sidx must hold >= 256 ints.
// ---------------------------------------------------------------------------
__device__ __forceinline__ int block_compact(const int* __restrict__ mask, int b,
                                             int* sidx, int* red, int pad){
    int t = threadIdx.x;
    int lane = t & 31, w = t >> 5;
    int keep = (mask[b*Kn + t] == 0);
    unsigned bal = __ballot_sync(0xffffffffu, keep);
    int rank = __popc(bal & ((1u << lane) - 1u));
    if (lane == 0) red[w] = __popc(bal);
    __syncthreads();
    int off = 0, total = 0;
    #pragma unroll
    for (int i = 0; i < 8; i++){ if (i < w) off += red[i]; total += red[i]; }
    if (keep) sidx[off + rank] = t;
    __syncthreads();
    int cntp = (total + pad - 1) & ~(pad - 1);
    int first = (total > 0) ? sidx[0] : 0;
    for (int i = total + t; i < cntp; i += 256) sidx[i] = first;
    if (total == 0)                // degenerate: treat all k as active
        for (int i = t; i < cntp; i += 256) sidx[i] = (i < Kn) ? i : 0;
    __syncthreads();
    return total;
}

// ---------------------------------------------------------------------------
// Kernel 1: projections, f32x2 FMA, single-sync double buffering.
// Tiles 0..15: query rows; tiles 16..47: compacted key rows (b1 folded).
// ---------------------------------------------------------------------------
__global__ __launch_bounds__(256) void proj_kernel(const float* __restrict__ query,
                                                   const float* __restrict__ key,
                                                   const float* __restrict__ W1,
                                                   const float* __restrict__ b1,
                                                   const int* __restrict__ mask){
    __shared__ float As[2][16][68];
    __shared__ float Ws[2][16][68];
    __shared__ int sidx[Kn];
    __shared__ int red[8];
    int tid = threadIdx.x;
    int colTile = blockIdx.x * 64;
    int tile = blockIdx.y;
    bool isQ = tile < (Bb*Qn/64);
    int arow = tid >> 2;
    int ac4  = (tid & 3) * 4;
    int b = 0, pos0 = 0;
    const float* Arow;
    if (isQ){
        Arow = query + (size_t)(tile*64 + arow)*Dd;
    } else {
        int t = tile - (Bb*Qn/64);
        b = t >> 2; pos0 = (t & 3) * 64;
        int cnt = block_compact(mask, b, sidx, red, 64);
        int cntp = (cnt + 63) & ~63;
        if (cnt == 0) cntp = Kn;       // degenerate fallback still projects all
        if (pos0 >= cntp) return;
        Arow = key + ((size_t)b*Kn + sidx[pos0 + arow])*Dd;
    }
    const float* W = W1 + (size_t)(isQ ? 0 : Dd)*Hh + colTile;
    int tx = tid & 15, ty = tid >> 4;
    int wrow = tid >> 4, wc4 = (tid & 15) * 4;

    u64 acc2[4][2];
    #pragma unroll
    for (int i = 0; i < 4; i++){ acc2[i][0] = 0ull; acc2[i][1] = 0ull; }

    float4 av = *(const float4*)(Arow + ac4);
    float4 wv = *(const float4*)(W + (size_t)wrow*Hh + wc4);

    const int NCH = Dd/16;
    for (int ch = 0; ch < NCH; ch++){
        int cur = ch & 1;
        As[cur][ac4+0][arow] = av.x; As[cur][ac4+1][arow] = av.y;
        As[cur][ac4+2][arow] = av.z; As[cur][ac4+3][arow] = av.w;
        *(float4*)&Ws[cur][wrow][wc4] = wv;
        __syncthreads();
        if (ch + 1 < NCH){
            int k0 = (ch + 1) * 16;
            av = *(const float4*)(Arow + k0 + ac4);
            wv = *(const float4*)(W + (size_t)(k0 + wrow)*Hh + wc4);
        }
        #pragma unroll
        for (int kk = 0; kk < 16; kk++){
            float4 a = *(const float4*)&As[cur][kk][ty*4];
            ulonglong2 bv = *(const ulonglong2*)&Ws[cur][kk][tx*4];
            u64 ad;
            ad = pack2(a.x,a.x); fma2(acc2[0][0],ad,bv.x); fma2(acc2[0][1],ad,bv.y);
            ad = pack2(a.y,a.y); fma2(acc2[1][0],ad,bv.x); fma2(acc2[1][1],ad,bv.y);
            ad = pack2(a.z,a.z); fma2(acc2[2][0],ad,bv.x); fma2(acc2[2][1],ad,bv.y);
            ad = pack2(a.w,a.w); fma2(acc2[3][0],ad,bv.x); fma2(acc2[3][1],ad,bv.y);
        }
    }

    if (isQ){
        float* outp = g_qproj + (size_t)(tile*64)*Hh + colTile;
        #pragma unroll
        for (int i = 0; i < 4; i++){
            float o0,o1,o2,o3;
            unpack2(acc2[i][0],o0,o1); unpack2(acc2[i][1],o2,o3);
            *(float4*)(outp + (size_t)(ty*4+i)*Hh + tx*4) = make_float4(o0,o1,o2,o3);
        }
    } else {
        float* outp = g_kproj + ((size_t)b*Kn + pos0)*Hh + colTile;
        float4 bb = *(const float4*)(b1 + colTile + tx*4);
        #pragma unroll
        for (int i = 0; i < 4; i++){
            float o0,o1,o2,o3;
            unpack2(acc2[i][0],o0,o1); unpack2(acc2[i][1],o2,o3);
            *(float4*)(outp + (size_t)(ty*4+i)*Hh + tx*4) =
                make_float4(o0+bb.x, o1+bb.y, o2+bb.z, o3+bb.w);
        }
    }
}

// ---------------------------------------------------------------------------
// Kernel 2: scores over compacted k. 16q x 32k per block, h-chunk 64
// (8 syncs), double-buffered. MUFU-bound; chip floor ~16us.
// ---------------------------------------------------------------------------
__global__ __launch_bounds__(256) void score_kernel(const float* __restrict__ w2,
                                                    const int* __restrict__ mask){
    __shared__ int sidx[Kn];
    __shared__ int red[8];
    int b  = blockIdx.z;
    int cnt = block_compact(mask, b, sidx, red, 64);
    int cntp = (cnt + 63) & ~63;
    if (cnt == 0) return;              // softmax handles all-masked rows
    int k0 = blockIdx.x * 32;
    if (k0 >= cntp) return;
    int q0 = blockIdx.y * 16;
    __shared__ float qs[2][64][17];
    __shared__ float ks[2][64][34];
    __shared__ float wsm[2][64];
    int tid = threadIdx.x;
    int tx = tid & 15;
    int ty = tid >> 4;
    const float* qbase = g_qproj + (size_t)(b*Qn + q0)*Hh;
    const float* kbase = g_kproj + ((size_t)b*Kn + k0)*Hh;

    float acc0 = 0.0f, acc1 = 0.0f;
    // loaders for 64-h chunk: q tile 16x64 (1024 f4-loads/4 = each of 256 thr
    // loads one float4); k tile 32x64 (512 float4 => 2 per thread)
    int qr = tid & 15,  qc4 = (tid >> 4) * 4;    // q row 0..15, h-col 0..60
    int kr = tid & 31,  kc8 = (tid >> 5) * 8;    // k row 0..31, h-col 0..56

    float4 qv4, kv4a, kv4b;
    float wv0 = 0.0f;
    qv4  = *(const float4*)(qbase + (size_t)qr*Hh + qc4);
    kv4a = *(const float4*)(kbase + (size_t)kr*Hh + kc8);
    kv4b = *(const float4*)(kbase + (size_t)kr*Hh + kc8 + 4);
    if (tid < 64) wv0 = w2[tid];

    const int NCH = Hh/64;
    for (int ch = 0; ch < NCH; ch++){
        int cur = ch & 1;
        qs[cur][qc4+0][qr] = qv4.x; qs[cur][qc4+1][qr] = qv4.y;
        qs[cur][qc4+2][qr] = qv4.z; qs[cur][qc4+3][qr] = qv4.w;
        ks[cur][kc8+0][kr] = kv4a.x; ks[cur][kc8+1][kr] = kv4a.y;
        ks[cur][kc8+2][kr] = kv4a.z; ks[cur][kc8+3][kr] = kv4a.w;
        ks[cur][kc8+4][kr] = kv4b.x; ks[cur][kc8+5][kr] = kv4b.y;
        ks[cur][kc8+6][kr] = kv4b.z; ks[cur][kc8+7][kr] = kv4b.w;
        if (tid < 64) wsm[cur][tid] = wv0;
        __syncthreads();
        if (ch + 1 < NCH){
            int h0 = (ch + 1) * 64;
            qv4  = *(const float4*)(qbase + (size_t)qr*Hh + h0 + qc4);
            kv4a = *(const float4*)(kbase + (size_t)kr*Hh + h0 + kc8);
            kv4b = *(const float4*)(kbase + (size_t)kr*Hh + h0 + kc8 + 4);
            if (tid < 64) wv0 = w2[h0 + tid];
        }
        #pragma unroll
        for (int h = 0; h < 64; h++){
            float wv = wsm[cur][h];
            float qv = qs[cur][h][ty];
            float2 kv = *(const float2*)&ks[cur][h][tx*2];
            acc0 += wv * fast_tanh(qv + kv.x);
            acc1 += wv * fast_tanh(qv + kv.y);
        }
    }
    int qq = b*Qn + q0 + ty;
    g_scores[(size_t)qq*Kn + sidx[k0 + tx*2+0]] = acc0 * RSQRT;
    g_scores[(size_t)qq*Kn + sidx[k0 + tx*2+1]] = acc1 * RSQRT;
}

// ---------------------------------------------------------------------------
// Kernel 3: row softmax; masked cols substituted in-register (exp -> 0).
// ---------------------------------------------------------------------------
__global__ __launch_bounds__(256) void softmax_kernel(const int* __restrict__ mask,
                                                      float* __restrict__ out_w){
    int row = blockIdx.x;
    int b = row >> 7;
    int t = threadIdx.x;
    int lane = t & 31, warp = t >> 5;
    __shared__ float red[8];
    float s = (mask[b*Kn + t] != 0) ? (-HUGEF * RSQRT)
                                    : g_scores[(size_t)row*Kn + t];
    float m = s;
    #pragma unroll
    for (int o = 16; o > 0; o >>= 1) m = fmaxf(m, __shfl_xor_sync(0xffffffffu, m, o));
    if (lane == 0) red[warp] = m;
    __syncthreads();
    float m8 = red[0];
    #pragma unroll
    for (int i = 1; i < 8; i++) m8 = fmaxf(m8, red[i]);
    float e = __expf(s - m8);
    float sum = e;
    #pragma unroll
    for (int o = 16; o > 0; o >>= 1) sum += __shfl_xor_sync(0xffffffffu, sum, o);
    __syncthreads();
    if (lane == 0) red[warp] = sum;
    __syncthreads();
    float s8 = 0.0f;
    #pragma unroll
    for (int i = 0; i < 8; i++) s8 += red[i];
    out_w[(size_t)row*Kn + t] = e / s8;
}

// ---------------------------------------------------------------------------
// Kernel 4: attn_vec GEMM over compacted k, f32x2, double-buffered.
// ---------------------------------------------------------------------------
__global__ __launch_bounds__(256) void attnvec_kernel(const float* __restrict__ value,
                                                      const float* __restrict__ attn_w,
                                                      float* __restrict__ out_v,
                                                      const int* __restrict__ mask){
    __shared__ float ws[2][16][33];
    __shared__ float vs[2][16][68];
    __shared__ int sidx[Kn];
    __shared__ int red[8];
    int b  = blockIdx.z;
    int q0 = blockIdx.y * 32;
    int v0 = blockIdx.x * 64;
    int tid = threadIdx.x;
    int tx = tid & 15, ty = tid >> 4;
    int cnt = block_compact(mask, b, sidx, red, 16);
    int n  = (cnt > 0) ? cnt : Kn;     // cnt==0: sidx filled 0..255 by helper
    int np = (n + 15) & ~15;

    int wq = tid >> 3, wk2 = (tid & 7) * 2;
    int vk = tid >> 4, vc4 = (tid & 15) * 4;
    const float* wrow  = attn_w + (size_t)(b*Qn + q0 + wq)*Kn;
    const float* vbase = value + (size_t)b*Kn*Vv + v0 + vc4;

    u64 acc2[2][2];
    acc2[0][0]=0ull; acc2[0][1]=0ull; acc2[1][0]=0ull; acc2[1][1]=0ull;

    float wr0, wr1; float4 vv;
    wr0 = (wk2+0 < n) ? wrow[sidx[wk2+0]] : 0.0f;
    wr1 = (wk2+1 < n) ? wrow[sidx[wk2+1]] : 0.0f;
    vv = *(const float4*)(vbase + (size_t)sidx[vk]*Vv);

    int nch = np / 16;
    for (int ch = 0; ch < nch; ch++){
        int cur = ch & 1;
        ws[cur][wk2+0][wq] = wr0;
        ws[cur][wk2+1][wq] = wr1;
        *(float4*)&vs[cur][vk][vc4] = vv;
        __syncthreads();
        if (ch + 1 < nch){
            int k0 = (ch + 1) * 16;
            wr0 = (k0+wk2+0 < n) ? wrow[sidx[k0+wk2+0]] : 0.0f;
            wr1 = (k0+wk2+1 < n) ? wrow[sidx[k0+wk2+1]] : 0.0f;
            vv = *(const float4*)(vbase + (size_t)sidx[k0+vk]*Vv);
        }
        #pragma unroll
        for (int kk = 0; kk < 16; kk++){
            float a0 = ws[cur][kk][ty*2+0];
            float a1 = ws[cur][kk][ty*2+1];
            ulonglong2 cv = *(const ulonglong2*)&vs[cur][kk][tx*4];
            u64 ad;
            ad = pack2(a0,a0); fma2(acc2[0][0],ad,cv.x); fma2(acc2[0][1],ad,cv.y);
            ad = pack2(a1,a1); fma2(acc2[1][0],ad,cv.x); fma2(acc2[1][1],ad,cv.y);
        }
    }

    float* outp = out_v + (size_t)(b*Qn + q0)*Vv + v0;
    #pragma unroll
    for (int i = 0; i < 2; i++){
        float o0,o1,o2,o3;
        unpack2(acc2[i][0],o0,o1); unpack2(acc2[i][1],o2,o3);
        *(float4*)(outp + (size_t)(ty*2+i)*Vv + tx*4) = make_float4(o0,o1,o2,o3);
    }
}

// ---------------------------------------------------------------------------
extern "C" void kernel_launch(void* const* d_in, const int* in_sizes, int n_in,
                              void* d_out, int out_size){
    const float* query = (const float*)d_in[0];
    const float* key_  = (const float*)d_in[1];
    const float* value = (const float*)d_in[2];
    const int*   mask  = (const int*)  d_in[3];
    const float* W1    = (const float*)d_in[4];
    const float* b1    = (const float*)d_in[5];
    const float* w2    = (const float*)d_in[6];

    float* out = (float*)d_out;
    float* out_vec = out;                       // (B,Q,V)
    float* out_w   = out + (size_t)Bb*Qn*Vv;    // (B,Q,K)

    dim3 gp(Hh/64, (Bb*Qn + Bb*Kn)/64);         // (8, 48); key tiles may exit
    proj_kernel<<<gp, 256>>>(query, key_, W1, b1, mask);

    dim3 g2(Kn/32, Qn/16, Bb);                  // (8, 8, 8); ~half exit
    score_kernel<<<g2, 256>>>(w2, mask);

    softmax_kernel<<<Bb*Qn, 256>>>(mask, out_w);

    dim3 g4(Vv/64, Qn/32, Bb);                  // (8, 4, 8)
    attnvec_kernel<<<g4, 256>>>(value, out_w, out_vec, mask);
}

// round 13
// speedup vs baseline: 1.1785x; 1.0362x over previous
#include <cuda_runtime.h>
#include <math.h>
#include <stdint.h>

#define Bb 8
#define Qn 128
#define Kn 256
#define Dd 512
#define Hh 512
#define Vv 512
#define HUGEF 1000000000.0f
#define RSQRT 0.04419417382415922f   // 1/sqrt(512)

// Scratch (allocation-free rule: __device__ globals)
__device__ float g_qproj[Bb*Qn*Hh];   // 2 MB
__device__ float g_kproj[Bb*Kn*Hh];   // 4 MB (compacted rows, b1 folded in)
__device__ float g_scores[Bb*Qn*Kn];  // 1 MB (only unmasked cols written)
__device__ int   g_kidx[Bb*Kn];       // compacted unmasked k indices (64-padded)
__device__ int   g_kcnt[Bb];

typedef unsigned long long u64;
__device__ __forceinline__ u64 pack2(float x, float y){
    u64 r; asm("mov.b64 %0, {%1,%2};" : "=l"(r) : "f"(x), "f"(y)); return r;
}
__device__ __forceinline__ void fma2(u64& d, u64 a, u64 b){
    asm("fma.rn.f32x2 %0, %1, %2, %0;" : "+l"(d) : "l"(a), "l"(b));
}
__device__ __forceinline__ void unpack2(u64 v, float& lo, float& hi){
    asm("mov.b64 {%0,%1}, %2;" : "=f"(lo), "=f"(hi) : "l"(v));
}
__device__ __forceinline__ float fast_tanh(float x){
    float r; asm("tanh.approx.f32 %0, %1;" : "=f"(r) : "f"(x)); return r;
}

// ---------------------------------------------------------------------------
// Kernel 0: per-batch compaction of unmasked k (64-padded with first index).
// ---------------------------------------------------------------------------
__global__ __launch_bounds__(256) void compact_kernel(const int* __restrict__ mask){
    int b = blockIdx.x, t = threadIdx.x;
    int lane = t & 31, w = t >> 5;
    int keep = (mask[b*Kn + t] == 0);
    unsigned bal = __ballot_sync(0xffffffffu, keep);
    int rank = __popc(bal & ((1u << lane) - 1u));
    __shared__ int wcnt[8];
    if (lane == 0) wcnt[w] = __popc(bal);
    __syncthreads();
    int off = 0, total = 0;
    #pragma unroll
    for (int i = 0; i < 8; i++){ if (i < w) off += wcnt[i]; total += wcnt[i]; }
    if (keep) g_kidx[b*Kn + off + rank] = t;
    __syncthreads();
    int cntp = (total + 63) & ~63;
    int first = (total > 0) ? g_kidx[b*Kn] : 0;
    for (int i = total + t; i < cntp; i += 256) g_kidx[b*Kn + i] = first;
    if (t == 0) g_kcnt[b] = total;
}

// ---------------------------------------------------------------------------
// Kernel 1: projections, f32x2 FMA, single-sync double buffering.
// Tiles 0..15: query rows; tiles 16..47: compacted key rows (b1 folded).
// ---------------------------------------------------------------------------
__global__ __launch_bounds__(256) void proj_kernel(const float* __restrict__ query,
                                                   const float* __restrict__ key,
                                                   const float* __restrict__ W1,
                                                   const float* __restrict__ b1){
    __shared__ float As[2][16][68];
    __shared__ float Ws[2][16][68];
    int tid = threadIdx.x;
    int colTile = blockIdx.x * 64;
    int tile = blockIdx.y;
    bool isQ = tile < (Bb*Qn/64);
    int arow = tid >> 2;
    int ac4  = (tid & 3) * 4;
    int b = 0, pos0 = 0;
    const float* Arow;
    if (isQ){
        Arow = query + (size_t)(tile*64 + arow)*Dd;
    } else {
        int t = tile - (Bb*Qn/64);
        b = t >> 2; pos0 = (t & 3) * 64;
        int cnt = g_kcnt[b];
        int cntp = (cnt + 63) & ~63;
        if (pos0 >= cntp) return;
        int kid = g_kidx[b*Kn + pos0 + arow];
        Arow = key + ((size_t)b*Kn + kid)*Dd;
    }
    const float* W = W1 + (size_t)(isQ ? 0 : Dd)*Hh + colTile;
    int tx = tid & 15, ty = tid >> 4;
    int wrow = tid >> 4, wc4 = (tid & 15) * 4;

    u64 acc2[4][2];
    #pragma unroll
    for (int i = 0; i < 4; i++){ acc2[i][0] = 0ull; acc2[i][1] = 0ull; }

    float4 av = *(const float4*)(Arow + ac4);
    float4 wv = *(const float4*)(W + (size_t)wrow*Hh + wc4);

    const int NCH = Dd/16;
    for (int ch = 0; ch < NCH; ch++){
        int cur = ch & 1;
        As[cur][ac4+0][arow] = av.x; As[cur][ac4+1][arow] = av.y;
        As[cur][ac4+2][arow] = av.z; As[cur][ac4+3][arow] = av.w;
        *(float4*)&Ws[cur][wrow][wc4] = wv;
        __syncthreads();
        if (ch + 1 < NCH){
            int k0 = (ch + 1) * 16;
            av = *(const float4*)(Arow + k0 + ac4);
            wv = *(const float4*)(W + (size_t)(k0 + wrow)*Hh + wc4);
        }
        #pragma unroll
        for (int kk = 0; kk < 16; kk++){
            float4 a = *(const float4*)&As[cur][kk][ty*4];
            ulonglong2 bv = *(const ulonglong2*)&Ws[cur][kk][tx*4];
            u64 ad;
            ad = pack2(a.x,a.x); fma2(acc2[0][0],ad,bv.x); fma2(acc2[0][1],ad,bv.y);
            ad = pack2(a.y,a.y); fma2(acc2[1][0],ad,bv.x); fma2(acc2[1][1],ad,bv.y);
            ad = pack2(a.z,a.z); fma2(acc2[2][0],ad,bv.x); fma2(acc2[2][1],ad,bv.y);
            ad = pack2(a.w,a.w); fma2(acc2[3][0],ad,bv.x); fma2(acc2[3][1],ad,bv.y);
        }
    }

    if (isQ){
        float* outp = g_qproj + (size_t)(tile*64)*Hh + colTile;
        #pragma unroll
        for (int i = 0; i < 4; i++){
            float o0,o1,o2,o3;
            unpack2(acc2[i][0],o0,o1); unpack2(acc2[i][1],o2,o3);
            *(float4*)(outp + (size_t)(ty*4+i)*Hh + tx*4) = make_float4(o0,o1,o2,o3);
        }
    } else {
        float* outp = g_kproj + ((size_t)b*Kn + pos0)*Hh + colTile;
        float4 bb = *(const float4*)(b1 + colTile + tx*4);
        #pragma unroll
        for (int i = 0; i < 4; i++){
            float o0,o1,o2,o3;
            unpack2(acc2[i][0],o0,o1); unpack2(acc2[i][1],o2,o3);
            *(float4*)(outp + (size_t)(ty*4+i)*Hh + tx*4) =
                make_float4(o0+bb.x, o1+bb.y, o2+bb.z, o3+bb.w);
        }
    }
}

// ---------------------------------------------------------------------------
// Kernel 2: scores over compacted k. 16q x 32k per block, h-chunk 32,
// double-buffered (R7 config: ~13KB smem, high occupancy). MUFU-bound.
// ---------------------------------------------------------------------------
__global__ __launch_bounds__(256) void score_kernel(const float* __restrict__ w2){
    int b  = blockIdx.z;
    int cnt = g_kcnt[b];
    int cntp = (cnt + 63) & ~63;
    int k0 = blockIdx.x * 32;
    if (k0 >= cntp) return;
    int q0 = blockIdx.y * 16;
    __shared__ float qs[2][32][17];
    __shared__ float ks[2][32][34];
    __shared__ float wsm[2][32];
    __shared__ int sidx[32];
    int tid = threadIdx.x;
    if (tid < 32) sidx[tid] = g_kidx[b*Kn + k0 + tid];
    int tx = tid & 15;
    int ty = tid >> 4;
    const float* qbase = g_qproj + (size_t)(b*Qn + q0)*Hh;
    const float* kbase = g_kproj + ((size_t)b*Kn + k0)*Hh;

    float acc0 = 0.0f, acc1 = 0.0f;
    int qr = tid >> 3, qc4 = (tid & 7) * 4;
    int kr = tid >> 3, kc4 = (tid & 7) * 4;

    float4 qv4 = make_float4(0,0,0,0), kv4;
    float wv0 = 0.0f;
    if (tid < 128) qv4 = *(const float4*)(qbase + (size_t)qr*Hh + qc4);
    kv4 = *(const float4*)(kbase + (size_t)kr*Hh + kc4);
    if (tid < 32) wv0 = w2[tid];

    const int NCH = Hh/32;
    for (int ch = 0; ch < NCH; ch++){
        int cur = ch & 1;
        if (tid < 128){
            qs[cur][qc4+0][qr] = qv4.x; qs[cur][qc4+1][qr] = qv4.y;
            qs[cur][qc4+2][qr] = qv4.z; qs[cur][qc4+3][qr] = qv4.w;
        }
        ks[cur][kc4+0][kr] = kv4.x; ks[cur][kc4+1][kr] = kv4.y;
        ks[cur][kc4+2][kr] = kv4.z; ks[cur][kc4+3][kr] = kv4.w;
        if (tid < 32) wsm[cur][tid] = wv0;
        __syncthreads();
        if (ch + 1 < NCH){
            int h0 = (ch + 1) * 32;
            if (tid < 128) qv4 = *(const float4*)(qbase + (size_t)qr*Hh + h0 + qc4);
            kv4 = *(const float4*)(kbase + (size_t)kr*Hh + h0 + kc4);
            if (tid < 32) wv0 = w2[h0 + tid];
        }
        #pragma unroll
        for (int h = 0; h < 32; h++){
            float wv = wsm[cur][h];
            float qv = qs[cur][h][ty];
            float2 kv = *(const float2*)&ks[cur][h][tx*2];
            acc0 += wv * fast_tanh(qv + kv.x);
            acc1 += wv * fast_tanh(qv + kv.y);
        }
    }
    int qq = b*Qn + q0 + ty;
    g_scores[(size_t)qq*Kn + sidx[tx*2+0]] = acc0 * RSQRT;
    g_scores[(size_t)qq*Kn + sidx[tx*2+1]] = acc1 * RSQRT;
}

// ---------------------------------------------------------------------------
// Kernel 3: row softmax; masked cols substituted in-register (exp -> 0).
// ---------------------------------------------------------------------------
__global__ __launch_bounds__(256) void softmax_kernel(const int* __restrict__ mask,
                                                      float* __restrict__ out_w){
    int row = blockIdx.x;
    int b = row >> 7;
    int t = threadIdx.x;
    int lane = t & 31, warp = t >> 5;
    __shared__ float red[8];
    float s = (mask[b*Kn + t] != 0) ? (-HUGEF * RSQRT)
                                    : g_scores[(size_t)row*Kn + t];
    float m = s;
    #pragma unroll
    for (int o = 16; o > 0; o >>= 1) m = fmaxf(m, __shfl_xor_sync(0xffffffffu, m, o));
    if (lane == 0) red[warp] = m;
    __syncthreads();
    float m8 = red[0];
    #pragma unroll
    for (int i = 1; i < 8; i++) m8 = fmaxf(m8, red[i]);
    float e = __expf(s - m8);
    float sum = e;
    #pragma unroll
    for (int o = 16; o > 0; o >>= 1) sum += __shfl_xor_sync(0xffffffffu, sum, o);
    __syncthreads();
    if (lane == 0) red[warp] = sum;
    __syncthreads();
    float s8 = 0.0f;
    #pragma unroll
    for (int i = 0; i < 8; i++) s8 += red[i];
    out_w[(size_t)row*Kn + t] = e / s8;
}

// ---------------------------------------------------------------------------
// Kernel 4: attn_vec DENSE GEMM (masked weights are exactly 0 after softmax,
// so no compaction needed — fully coalesced, no gather, no sidx, no mask).
// 32q x 64v tiles, micro 2q x 4v, f32x2, single-sync double-buffered.
// ---------------------------------------------------------------------------
__global__ __launch_bounds__(256) void attnvec_kernel(const float* __restrict__ value,
                                                      const float* __restrict__ attn_w,
                                                      float* __restrict__ out_v){
    __shared__ float ws[2][16][33];
    __shared__ float vs[2][16][68];
    int b  = blockIdx.z;
    int q0 = blockIdx.y * 32;
    int v0 = blockIdx.x * 64;
    int tid = threadIdx.x;
    int tx = tid & 15, ty = tid >> 4;

    int wq = tid >> 3, wk2 = (tid & 7) * 2;   // w tile: 32q x 16k, float2/thread
    int vk = tid >> 4, vc4 = (tid & 15) * 4;  // v tile: 16k x 64v, float4/thread
    const float* wrow  = attn_w + (size_t)(b*Qn + q0 + wq)*Kn;
    const float* vbase = value + (size_t)b*Kn*Vv + v0 + vc4;

    u64 acc2[2][2];
    acc2[0][0]=0ull; acc2[0][1]=0ull; acc2[1][0]=0ull; acc2[1][1]=0ull;

    float2 wr = *(const float2*)(wrow + wk2);
    float4 vv = *(const float4*)(vbase + (size_t)vk*Vv);

    const int NCH = Kn/16;
    for (int ch = 0; ch < NCH; ch++){
        int cur = ch & 1;
        ws[cur][wk2+0][wq] = wr.x;
        ws[cur][wk2+1][wq] = wr.y;
        *(float4*)&vs[cur][vk][vc4] = vv;
        __syncthreads();
        if (ch + 1 < NCH){
            int k0 = (ch + 1) * 16;
            wr = *(const float2*)(wrow + k0 + wk2);
            vv = *(const float4*)(vbase + (size_t)(k0 + vk)*Vv);
        }
        #pragma unroll
        for (int kk = 0; kk < 16; kk++){
            float a0 = ws[cur][kk][ty*2+0];
            float a1 = ws[cur][kk][ty*2+1];
            ulonglong2 cv = *(const ulonglong2*)&vs[cur][kk][tx*4];
            u64 ad;
            ad = pack2(a0,a0); fma2(acc2[0][0],ad,cv.x); fma2(acc2[0][1],ad,cv.y);
            ad = pack2(a1,a1); fma2(acc2[1][0],ad,cv.x); fma2(acc2[1][1],ad,cv.y);
        }
    }

    float* outp = out_v + (size_t)(b*Qn + q0)*Vv + v0;
    #pragma unroll
    for (int i = 0; i < 2; i++){
        float o0,o1,o2,o3;
        unpack2(acc2[i][0],o0,o1); unpack2(acc2[i][1],o2,o3);
        *(float4*)(outp + (size_t)(ty*2+i)*Vv + tx*4) = make_float4(o0,o1,o2,o3);
    }
}

// ---------------------------------------------------------------------------
extern "C" void kernel_launch(void* const* d_in, const int* in_sizes, int n_in,
                              void* d_out, int out_size){
    const float* query = (const float*)d_in[0];
    const float* key_  = (const float*)d_in[1];
    const float* value = (const float*)d_in[2];
    const int*   mask  = (const int*)  d_in[3];
    const float* W1    = (const float*)d_in[4];
    const float* b1    = (const float*)d_in[5];
    const float* w2    = (const float*)d_in[6];

    float* out = (float*)d_out;
    float* out_vec = out;                       // (B,Q,V)
    float* out_w   = out + (size_t)Bb*Qn*Vv;    // (B,Q,K)

    compact_kernel<<<Bb, 256>>>(mask);

    dim3 gp(Hh/64, (Bb*Qn + Bb*Kn)/64);         // (8, 48); key tiles may exit
    proj_kernel<<<gp, 256>>>(query, key_, W1, b1);

    dim3 g2(Kn/32, Qn/16, Bb);                  // (8, 8, 8); ~half exit
    score_kernel<<<g2, 256>>>(w2);

    softmax_kernel<<<Bb*Qn, 256>>>(mask, out_w);

    dim3 g4(Vv/64, Qn/32, Bb);                  // (8, 4, 8)
    attnvec_kernel<<<g4, 256>>>(value, out_w, out_vec);
}

// round 16
// speedup vs baseline: 1.4541x; 1.2339x over previous
#include <cuda_runtime.h>
#include <math.h>
#include <stdint.h>

#define Bb 8
#define Qn 128
#define Kn 256
#define Dd 512
#define Hh 512
#define Vv 512
#define HUGEF 1000000000.0f
#define RSQRT 0.04419417382415922f   // 1/sqrt(512)

// Scratch (allocation-free rule: __device__ globals)
__device__ float g_qproj[Bb*Qn*Hh];   // 2 MB
__device__ float g_kproj[Bb*Kn*Hh];   // 4 MB (compacted rows, b1 folded in)
__device__ int   g_kidx[Bb*Kn];       // compacted unmasked k indices (128-padded)
__device__ int   g_kcnt[Bb];

typedef unsigned long long u64;
__device__ __forceinline__ u64 pack2(float x, float y){
    u64 r; asm("mov.b64 %0, {%1,%2};" : "=l"(r) : "f"(x), "f"(y)); return r;
}
__device__ __forceinline__ void fma2(u64& d, u64 a, u64 b){
    asm("fma.rn.f32x2 %0, %1, %2, %0;" : "+l"(d) : "l"(a), "l"(b));
}
__device__ __forceinline__ void unpack2(u64 v, float& lo, float& hi){
    asm("mov.b64 {%0,%1}, %2;" : "=f"(lo), "=f"(hi) : "l"(v));
}
__device__ __forceinline__ float fast_tanh(float x){
    float r; asm("tanh.approx.f32 %0, %1;" : "=f"(r) : "f"(x)); return r;
}

// ---------------------------------------------------------------------------
// Kernel 0: per-batch compaction of unmasked k (128-padded with first index).
// ---------------------------------------------------------------------------
__global__ __launch_bounds__(256) void compact_kernel(const int* __restrict__ mask){
    int b = blockIdx.x, t = threadIdx.x;
    int lane = t & 31, w = t >> 5;
    int keep = (mask[b*Kn + t] == 0);
    unsigned bal = __ballot_sync(0xffffffffu, keep);
    int rank = __popc(bal & ((1u << lane) - 1u));
    __shared__ int wcnt[8];
    if (lane == 0) wcnt[w] = __popc(bal);
    __syncthreads();
    int off = 0, total = 0;
    #pragma unroll
    for (int i = 0; i < 8; i++){ if (i < w) off += wcnt[i]; total += wcnt[i]; }
    if (keep) g_kidx[b*Kn + off + rank] = t;
    __syncthreads();
    int cntp = (total + 127) & ~127;
    int first = (total > 0) ? g_kidx[b*Kn] : 0;
    for (int i = total + t; i < cntp; i += 256) g_kidx[b*Kn + i] = first;
    if (t == 0) g_kcnt[b] = total;
}

// ---------------------------------------------------------------------------
// Kernel 1: projections, f32x2 FMA, single-sync double buffering.
// Tiles 0..15: query rows; tiles 16..47: compacted key rows (b1 folded),
// padded to 128 so downstream sees defined rows.
// ---------------------------------------------------------------------------
__global__ __launch_bounds__(256) void proj_kernel(const float* __restrict__ query,
                                                   const float* __restrict__ key,
                                                   const float* __restrict__ W1,
                                                   const float* __restrict__ b1){
    __shared__ float As[2][16][68];
    __shared__ float Ws[2][16][68];
    int tid = threadIdx.x;
    int colTile = blockIdx.x * 64;
    int tile = blockIdx.y;
    bool isQ = tile < (Bb*Qn/64);
    int arow = tid >> 2;
    int ac4  = (tid & 3) * 4;
    int b = 0, pos0 = 0;
    const float* Arow;
    if (isQ){
        Arow = query + (size_t)(tile*64 + arow)*Dd;
    } else {
        int t = tile - (Bb*Qn/64);
        b = t >> 2; pos0 = (t & 3) * 64;
        int cnt = g_kcnt[b];
        int cntp = (cnt + 127) & ~127;      // 128-pad (fused reads up to pad32<=pad128)
        if (pos0 >= cntp) return;
        int kid = g_kidx[b*Kn + pos0 + arow];
        Arow = key + ((size_t)b*Kn + kid)*Dd;
    }
    const float* W = W1 + (size_t)(isQ ? 0 : Dd)*Hh + colTile;
    int tx = tid & 15, ty = tid >> 4;
    int wrow = tid >> 4, wc4 = (tid & 15) * 4;

    u64 acc2[4][2];
    #pragma unroll
    for (int i = 0; i < 4; i++){ acc2[i][0] = 0ull; acc2[i][1] = 0ull; }

    float4 av = *(const float4*)(Arow + ac4);
    float4 wv = *(const float4*)(W + (size_t)wrow*Hh + wc4);

    const int NCH = Dd/16;
    for (int ch = 0; ch < NCH; ch++){
        int cur = ch & 1;
        As[cur][ac4+0][arow] = av.x; As[cur][ac4+1][arow] = av.y;
        As[cur][ac4+2][arow] = av.z; As[cur][ac4+3][arow] = av.w;
        *(float4*)&Ws[cur][wrow][wc4] = wv;
        __syncthreads();
        if (ch + 1 < NCH){
            int k0 = (ch + 1) * 16;
            av = *(const float4*)(Arow + k0 + ac4);
            wv = *(const float4*)(W + (size_t)(k0 + wrow)*Hh + wc4);
        }
        #pragma unroll
        for (int kk = 0; kk < 16; kk++){
            float4 a = *(const float4*)&As[cur][kk][ty*4];
            ulonglong2 bv = *(const ulonglong2*)&Ws[cur][kk][tx*4];
            u64 ad;
            ad = pack2(a.x,a.x); fma2(acc2[0][0],ad,bv.x); fma2(acc2[0][1],ad,bv.y);
            ad = pack2(a.y,a.y); fma2(acc2[1][0],ad,bv.x); fma2(acc2[1][1],ad,bv.y);
            ad = pack2(a.z,a.z); fma2(acc2[2][0],ad,bv.x); fma2(acc2[2][1],ad,bv.y);
            ad = pack2(a.w,a.w); fma2(acc2[3][0],ad,bv.x); fma2(acc2[3][1],ad,bv.y);
        }
    }

    if (isQ){
        float* outp = g_qproj + (size_t)(tile*64)*Hh + colTile;
        #pragma unroll
        for (int i = 0; i < 4; i++){
            float o0,o1,o2,o3;
            unpack2(acc2[i][0],o0,o1); unpack2(acc2[i][1],o2,o3);
            *(float4*)(outp + (size_t)(ty*4+i)*Hh + tx*4) = make_float4(o0,o1,o2,o3);
        }
    } else {
        float* outp = g_kproj + ((size_t)b*Kn + pos0)*Hh + colTile;
        float4 bb = *(const float4*)(b1 + colTile + tx*4);
        #pragma unroll
        for (int i = 0; i < 4; i++){
            float o0,o1,o2,o3;
            unpack2(acc2[i][0],o0,o1); unpack2(acc2[i][1],o2,o3);
            *(float4*)(outp + (size_t)(ty*4+i)*Hh + tx*4) =
                make_float4(o0+bb.x, o1+bb.y, o2+bb.z, o3+bb.w);
        }
    }
}

// ---------------------------------------------------------------------------
// Fused score+softmax+attnvec kernel. Grid (Qn/8=16, Bb=8)=128 blocks,
// 256 threads. Dynamic smem layout (floats):
//   qs   [0,4096)      8x512 q-slab (loaded once)
//   ws2  [4096,4608)   w2
//   sw   [4608,6656)   scores->weights [8][256]
//   sidx [6656,6912)   compacted indices (int)
//   ks2  [6912,23808)  2 x (256 k x 32 h, stride 33) staging
//   swp  [23808,27904) packed f32x2 weights [8][256] (u64)
// ---------------------------------------------------------------------------
#define FUSED_SMEM (27904*4)

template<int MM>
__device__ __forceinline__ void phase1_run(const float* __restrict__ kbase,
                                           const float* qs, const float* ws2,
                                           float* ks2, float* sw){
    int tid = threadIdx.x;
    int q = tid >> 5, k4 = tid & 31;
    float acc[MM];
    #pragma unroll
    for (int m = 0; m < MM; m++) acc[m] = 0.0f;
    float4 pf[MM];
    #pragma unroll
    for (int u = 0; u < MM; u++){
        int e = tid*4 + u*1024;
        pf[u] = *(const float4*)(kbase + (size_t)(e>>5)*Hh + (e&31));
    }
    for (int hc = 0; hc < 16; hc++){
        float* kb = ks2 + (hc & 1)*8448;
        #pragma unroll
        for (int u = 0; u < MM; u++){
            int e = tid*4 + u*1024;
            int r = e>>5, h = e&31;
            kb[r*33+h+0] = pf[u].x; kb[r*33+h+1] = pf[u].y;
            kb[r*33+h+2] = pf[u].z; kb[r*33+h+3] = pf[u].w;
        }
        __syncthreads();
        if (hc + 1 < 16){
            int h0 = (hc + 1)*32;
            #pragma unroll
            for (int u = 0; u < MM; u++){
                int e = tid*4 + u*1024;
                pf[u] = *(const float4*)(kbase + (size_t)(e>>5)*Hh + h0 + (e&31));
            }
        }
        #pragma unroll
        for (int h = 0; h < 32; h++){
            float wv = ws2[hc*32 + h];
            float qv = qs[q*512 + hc*32 + h];
            #pragma unroll
            for (int m = 0; m < MM; m++){
                float kv = kb[(k4 + 32*m)*33 + h];
                acc[m] += wv * fast_tanh(qv + kv);
            }
        }
    }
    #pragma unroll
    for (int m = 0; m < MM; m++)
        sw[q*256 + k4 + 32*m] = acc[m] * RSQRT;
}

__global__ __launch_bounds__(256) void fused_kernel(const float* __restrict__ value,
                                                    const float* __restrict__ w2,
                                                    float* __restrict__ out_w,
                                                    float* __restrict__ out_v){
    extern __shared__ float sm[];
    float* qs  = sm;
    float* ws2 = sm + 4096;
    float* sw  = sm + 4608;
    int*   sidx = (int*)(sm + 6656);
    float* ks2 = sm + 6912;
    u64*   swp = (u64*)(sm + 23808);

    int b = blockIdx.y, q0 = blockIdx.x * 8;
    int tid = threadIdx.x, lane = tid & 31, wp = tid >> 5;
    int cnt = g_kcnt[b];
    size_t orow = (size_t)(b*Qn + q0);

    // load q slab (rows contiguous in g_qproj), w2, sidx
    const float* qg = g_qproj + orow*Hh;
    #pragma unroll
    for (int i = 0; i < 4; i++){
        int e = tid*4 + i*1024;
        *(float4*)&qs[e] = *(const float4*)(qg + e);
    }
    ws2[tid] = w2[tid]; ws2[tid + 256] = w2[tid + 256];
    for (int i = tid; i < Kn; i += 256) sidx[i] = g_kidx[b*Kn + i];
    __syncthreads();

    if (cnt > 0){
        int cntp = (cnt + 31) & ~31;
        int M = cntp >> 5;                 // 1..8
        const float* kbase = g_kproj + (size_t)(b*Kn)*Hh;
        switch (M){
            case 1: phase1_run<1>(kbase, qs, ws2, ks2, sw); break;
            case 2: phase1_run<2>(kbase, qs, ws2, ks2, sw); break;
            case 3: phase1_run<3>(kbase, qs, ws2, ks2, sw); break;
            case 4: phase1_run<4>(kbase, qs, ws2, ks2, sw); break;
            case 5: phase1_run<5>(kbase, qs, ws2, ks2, sw); break;
            case 6: phase1_run<6>(kbase, qs, ws2, ks2, sw); break;
            case 7: phase1_run<7>(kbase, qs, ws2, ks2, sw); break;
            default: phase1_run<8>(kbase, qs, ws2, ks2, sw); break;
        }
        __syncthreads();

        // phase 2: softmax, one warp per q row (8 warps = 8 rows)
        {
            int q = wp;
            float* row = sw + q*256;
            float mmax = -3.0e38f;
            for (int i = lane; i < cnt; i += 32) mmax = fmaxf(mmax, row[i]);
            #pragma unroll
            for (int o = 16; o > 0; o >>= 1) mmax = fmaxf(mmax, __shfl_xor_sync(0xffffffffu, mmax, o));
            float ssum = 0.0f;
            for (int i = lane; i < cnt; i += 32){
                float e = __expf(row[i] - mmax); row[i] = e; ssum += e;
            }
            #pragma unroll
            for (int o = 16; o > 0; o >>= 1) ssum += __shfl_xor_sync(0xffffffffu, ssum, o);
            float inv = 1.0f / ssum;
            for (int i = lane; i < cnt; i += 32){
                float wgt = row[i] * inv; row[i] = wgt; swp[q*256 + i] = pack2(wgt, wgt);
            }
        }
        // dense zeros for attn_weights rows
        float* owbase = out_w + orow*Kn;
        #pragma unroll
        for (int i = 0; i < 2; i++)
            ((float4*)owbase)[tid + i*256] = make_float4(0.f,0.f,0.f,0.f);
        __syncthreads();
        // scatter active weights
        for (int e = tid; e < 8*256; e += 256){
            int q = e >> 8, i = e & 255;
            if (i < cnt) owbase[(size_t)q*Kn + sidx[i]] = sw[q*256 + i];
        }
    } else {
        // all-masked: uniform weights, attn over all value rows
        const float wu = 1.0f / (float)Kn;
        for (int i = tid; i < Kn; i += 256) sidx[i] = i;
        for (int e = tid; e < 8*256; e += 256){ sw[e] = wu; swp[e] = pack2(wu, wu); }
        float* owbase = out_w + orow*Kn;
        #pragma unroll
        for (int i = 0; i < 2; i++)
            ((float4*)owbase)[tid + i*256] = make_float4(wu,wu,wu,wu);
        cnt = Kn;
        __syncthreads();
    }

    // phase 3: attn_vec, thread covers v cols (2*tid, 2*tid+1) for all 8 q
    u64 acc2[8];
    #pragma unroll
    for (int q = 0; q < 8; q++) acc2[q] = 0ull;
    const float* vb = value + (size_t)b*Kn*Vv + 2*tid;
    #pragma unroll 4
    for (int i = 0; i < cnt; i++){
        u64 vv = *(const u64*)(vb + (size_t)sidx[i]*Vv);
        #pragma unroll
        for (int q = 0; q < 8; q++) fma2(acc2[q], swp[q*256 + i], vv);
    }
    float* ovbase = out_v + orow*Vv + 2*tid;
    #pragma unroll
    for (int q = 0; q < 8; q++){
        float lo, hi; unpack2(acc2[q], lo, hi);
        *(float2*)(ovbase + (size_t)q*Vv) = make_float2(lo, hi);
    }
}

// ---------------------------------------------------------------------------
extern "C" void kernel_launch(void* const* d_in, const int* in_sizes, int n_in,
                              void* d_out, int out_size){
    const float* query = (const float*)d_in[0];
    const float* key_  = (const float*)d_in[1];
    const float* value = (const float*)d_in[2];
    const int*   mask  = (const int*)  d_in[3];
    const float* W1    = (const float*)d_in[4];
    const float* b1    = (const float*)d_in[5];
    const float* w2    = (const float*)d_in[6];

    float* out = (float*)d_out;
    float* out_vec = out;                       // (B,Q,V)
    float* out_w   = out + (size_t)Bb*Qn*Vv;    // (B,Q,K)

    cudaFuncSetAttribute(fused_kernel,
                         cudaFuncAttributeMaxDynamicSharedMemorySize, FUSED_SMEM);

    compact_kernel<<<Bb, 256>>>(mask);

    dim3 gp(Hh/64, (Bb*Qn + Bb*Kn)/64);         // (8, 48); key tiles may exit
    proj_kernel<<<gp, 256>>>(query, key_, W1, b1);

    dim3 gf(Qn/8, Bb);                          // (16, 8) = 128 blocks
    fused_kernel<<<gf, 256, FUSED_SMEM>>>(value, w2, out_w, out_vec);
}

// round 17
// speedup vs baseline: 1.4736x; 1.0134x over previous
#include <cuda_runtime.h>
#include <math.h>
#include <stdint.h>

#define Bb 8
#define Qn 128
#define Kn 256
#define Dd 512
#define Hh 512
#define Vv 512
#define HUGEF 1000000000.0f
#define RSQRT 0.04419417382415922f   // 1/sqrt(512)

// Scratch (allocation-free rule: __device__ globals)
__device__ float g_qproj[Bb*Qn*Hh];   // 2 MB
__device__ float g_kproj[Bb*Kn*Hh];   // 4 MB (compacted rows, b1 folded in)
__device__ int   g_kidx[Bb*Kn];       // compacted unmasked k indices
__device__ int   g_kcnt[Bb];

typedef unsigned long long u64;
__device__ __forceinline__ u64 pack2(float x, float y){
    u64 r; asm("mov.b64 %0, {%1,%2};" : "=l"(r) : "f"(x), "f"(y)); return r;
}
__device__ __forceinline__ void fma2(u64& d, u64 a, u64 b){
    asm("fma.rn.f32x2 %0, %1, %2, %0;" : "+l"(d) : "l"(a), "l"(b));
}
__device__ __forceinline__ void unpack2(u64 v, float& lo, float& hi){
    asm("mov.b64 {%0,%1}, %2;" : "=f"(lo), "=f"(hi) : "l"(v));
}
__device__ __forceinline__ float fast_tanh(float x){
    float r; asm("tanh.approx.f32 %0, %1;" : "=f"(r) : "f"(x)); return r;
}

// ---------------------------------------------------------------------------
// Kernel 1: projections, f32x2 FMA, single-sync double buffering.
// Tiles 0..15: query rows; tiles 16..47: compacted key rows (b1 folded),
// padded to 128. Key tiles compute the compaction locally (~500 cyc, mask is
// L2-resident); the (colTile==0, chunk==0) block per batch publishes
// g_kidx/g_kcnt for the fused kernel — BEFORE its early-exit, so cnt==0
// still publishes. Replaces the separate compact kernel (-~5us launch).
// ---------------------------------------------------------------------------
__global__ __launch_bounds__(256) void proj_kernel(const float* __restrict__ query,
                                                   const float* __restrict__ key,
                                                   const float* __restrict__ W1,
                                                   const float* __restrict__ b1,
                                                   const int* __restrict__ mask){
    __shared__ float As[2][16][68];
    __shared__ float Ws[2][16][68];
    __shared__ int sidx[Kn];
    __shared__ int red[8];
    int tid = threadIdx.x;
    int colTile = blockIdx.x * 64;
    int tile = blockIdx.y;
    bool isQ = tile < (Bb*Qn/64);
    int arow = tid >> 2;
    int ac4  = (tid & 3) * 4;
    int b = 0, pos0 = 0;
    const float* Arow;
    if (isQ){
        Arow = query + (size_t)(tile*64 + arow)*Dd;
    } else {
        int t = tile - (Bb*Qn/64);
        b = t >> 2; pos0 = (t & 3) * 64;
        // ---- local compaction (all key blocks; whole block, no divergence)
        {
            int lane = tid & 31, w = tid >> 5;
            int keep = (mask[b*Kn + tid] == 0);
            unsigned bal = __ballot_sync(0xffffffffu, keep);
            int rank = __popc(bal & ((1u << lane) - 1u));
            if (lane == 0) red[w] = __popc(bal);
            __syncthreads();
            int off = 0, total = 0;
            #pragma unroll
            for (int i = 0; i < 8; i++){ if (i < w) off += red[i]; total += red[i]; }
            if (keep) sidx[off + rank] = tid;
            __syncthreads();
            int cntp = (total + 127) & ~127;
            int first = (total > 0) ? sidx[0] : 0;
            for (int i = total + tid; i < cntp; i += 256) sidx[i] = first;
            __syncthreads();
            // publisher: one block per batch writes global compaction
            if (blockIdx.x == 0 && pos0 == 0){
                if (tid == 0) g_kcnt[b] = total;
                for (int i = tid; i < total; i += 256) g_kidx[b*Kn + i] = sidx[i];
            }
            int cnt = total;
            int cap = (cnt + 127) & ~127;
            if (pos0 >= cap) return;
        }
        Arow = key + ((size_t)b*Kn + sidx[pos0 + arow])*Dd;
    }
    const float* W = W1 + (size_t)(isQ ? 0 : Dd)*Hh + colTile;
    int tx = tid & 15, ty = tid >> 4;
    int wrow = tid >> 4, wc4 = (tid & 15) * 4;

    u64 acc2[4][2];
    #pragma unroll
    for (int i = 0; i < 4; i++){ acc2[i][0] = 0ull; acc2[i][1] = 0ull; }

    float4 av = *(const float4*)(Arow + ac4);
    float4 wv = *(const float4*)(W + (size_t)wrow*Hh + wc4);

    const int NCH = Dd/16;
    for (int ch = 0; ch < NCH; ch++){
        int cur = ch & 1;
        As[cur][ac4+0][arow] = av.x; As[cur][ac4+1][arow] = av.y;
        As[cur][ac4+2][arow] = av.z; As[cur][ac4+3][arow] = av.w;
        *(float4*)&Ws[cur][wrow][wc4] = wv;
        __syncthreads();
        if (ch + 1 < NCH){
            int k0 = (ch + 1) * 16;
            av = *(const float4*)(Arow + k0 + ac4);
            wv = *(const float4*)(W + (size_t)(k0 + wrow)*Hh + wc4);
        }
        #pragma unroll
        for (int kk = 0; kk < 16; kk++){
            float4 a = *(const float4*)&As[cur][kk][ty*4];
            ulonglong2 bv = *(const ulonglong2*)&Ws[cur][kk][tx*4];
            u64 ad;
            ad = pack2(a.x,a.x); fma2(acc2[0][0],ad,bv.x); fma2(acc2[0][1],ad,bv.y);
            ad = pack2(a.y,a.y); fma2(acc2[1][0],ad,bv.x); fma2(acc2[1][1],ad,bv.y);
            ad = pack2(a.z,a.z); fma2(acc2[2][0],ad,bv.x); fma2(acc2[2][1],ad,bv.y);
            ad = pack2(a.w,a.w); fma2(acc2[3][0],ad,bv.x); fma2(acc2[3][1],ad,bv.y);
        }
    }

    if (isQ){
        float* outp = g_qproj + (size_t)(tile*64)*Hh + colTile;
        #pragma unroll
        for (int i = 0; i < 4; i++){
            float o0,o1,o2,o3;
            unpack2(acc2[i][0],o0,o1); unpack2(acc2[i][1],o2,o3);
            *(float4*)(outp + (size_t)(ty*4+i)*Hh + tx*4) = make_float4(o0,o1,o2,o3);
        }
    } else {
        float* outp = g_kproj + ((size_t)b*Kn + pos0)*Hh + colTile;
        float4 bb = *(const float4*)(b1 + colTile + tx*4);
        #pragma unroll
        for (int i = 0; i < 4; i++){
            float o0,o1,o2,o3;
            unpack2(acc2[i][0],o0,o1); unpack2(acc2[i][1],o2,o3);
            *(float4*)(outp + (size_t)(ty*4+i)*Hh + tx*4) =
                make_float4(o0+bb.x, o1+bb.y, o2+bb.z, o3+bb.w);
        }
    }
}

// ---------------------------------------------------------------------------
// Fused score+softmax+attnvec kernel. Grid (Qn/8=16, Bb=8)=128 blocks,
// 256 threads. Dynamic smem layout (floats):
//   qs   [0,4096)      8x512 q-slab (loaded once)
//   ws2  [4096,4608)   w2
//   sw   [4608,6656)   scores->weights [8][256]
//   sidx [6656,6912)   compacted indices (int)
//   ks2  [6912,23808)  2 x (256 k x 32 h, stride 33) staging
//   swp  [23808,27904) packed f32x2 weights [8][256] (u64)
// ---------------------------------------------------------------------------
#define FUSED_SMEM (27904*4)

template<int MM>
__device__ __forceinline__ void phase1_run(const float* __restrict__ kbase,
                                           const float* qs, const float* ws2,
                                           float* ks2, float* sw){
    int tid = threadIdx.x;
    int q = tid >> 5, k4 = tid & 31;
    float acc[MM];
    #pragma unroll
    for (int m = 0; m < MM; m++) acc[m] = 0.0f;
    float4 pf[MM];
    #pragma unroll
    for (int u = 0; u < MM; u++){
        int e = tid*4 + u*1024;
        pf[u] = *(const float4*)(kbase + (size_t)(e>>5)*Hh + (e&31));
    }
    for (int hc = 0; hc < 16; hc++){
        float* kb = ks2 + (hc & 1)*8448;
        #pragma unroll
        for (int u = 0; u < MM; u++){
            int e = tid*4 + u*1024;
            int r = e>>5, h = e&31;
            kb[r*33+h+0] = pf[u].x; kb[r*33+h+1] = pf[u].y;
            kb[r*33+h+2] = pf[u].z; kb[r*33+h+3] = pf[u].w;
        }
        __syncthreads();
        if (hc + 1 < 16){
            int h0 = (hc + 1)*32;
            #pragma unroll
            for (int u = 0; u < MM; u++){
                int e = tid*4 + u*1024;
                pf[u] = *(const float4*)(kbase + (size_t)(e>>5)*Hh + h0 + (e&31));
            }
        }
        #pragma unroll
        for (int h = 0; h < 32; h++){
            float wv = ws2[hc*32 + h];
            float qv = qs[q*512 + hc*32 + h];
            #pragma unroll
            for (int m = 0; m < MM; m++){
                float kv = kb[(k4 + 32*m)*33 + h];
                acc[m] += wv * fast_tanh(qv + kv);
            }
        }
    }
    #pragma unroll
    for (int m = 0; m < MM; m++)
        sw[q*256 + k4 + 32*m] = acc[m] * RSQRT;
}

__global__ __launch_bounds__(256) void fused_kernel(const float* __restrict__ value,
                                                    const float* __restrict__ w2,
                                                    float* __restrict__ out_w,
                                                    float* __restrict__ out_v){
    extern __shared__ float sm[];
    float* qs  = sm;
    float* ws2 = sm + 4096;
    float* sw  = sm + 4608;
    int*   sidx = (int*)(sm + 6656);
    float* ks2 = sm + 6912;
    u64*   swp = (u64*)(sm + 23808);

    int b = blockIdx.y, q0 = blockIdx.x * 8;
    int tid = threadIdx.x, lane = tid & 31, wp = tid >> 5;
    int cnt = g_kcnt[b];
    size_t orow = (size_t)(b*Qn + q0);

    // load q slab (rows contiguous in g_qproj), w2, sidx
    const float* qg = g_qproj + orow*Hh;
    #pragma unroll
    for (int i = 0; i < 4; i++){
        int e = tid*4 + i*1024;
        *(float4*)&qs[e] = *(const float4*)(qg + e);
    }
    ws2[tid] = w2[tid]; ws2[tid + 256] = w2[tid + 256];
    for (int i = tid; i < Kn; i += 256) sidx[i] = g_kidx[b*Kn + i];
    __syncthreads();

    if (cnt > 0){
        int cntp = (cnt + 31) & ~31;
        int M = cntp >> 5;                 // 1..8
        const float* kbase = g_kproj + (size_t)(b*Kn)*Hh;
        switch (M){
            case 1: phase1_run<1>(kbase, qs, ws2, ks2, sw); break;
            case 2: phase1_run<2>(kbase, qs, ws2, ks2, sw); break;
            case 3: phase1_run<3>(kbase, qs, ws2, ks2, sw); break;
            case 4: phase1_run<4>(kbase, qs, ws2, ks2, sw); break;
            case 5: phase1_run<5>(kbase, qs, ws2, ks2, sw); break;
            case 6: phase1_run<6>(kbase, qs, ws2, ks2, sw); break;
            case 7: phase1_run<7>(kbase, qs, ws2, ks2, sw); break;
            default: phase1_run<8>(kbase, qs, ws2, ks2, sw); break;
        }
        __syncthreads();

        // phase 2: softmax, one warp per q row (8 warps = 8 rows)
        {
            int q = wp;
            float* row = sw + q*256;
            float mmax = -3.0e38f;
            for (int i = lane; i < cnt; i += 32) mmax = fmaxf(mmax, row[i]);
            #pragma unroll
            for (int o = 16; o > 0; o >>= 1) mmax = fmaxf(mmax, __shfl_xor_sync(0xffffffffu, mmax, o));
            float ssum = 0.0f;
            for (int i = lane; i < cnt; i += 32){
                float e = __expf(row[i] - mmax); row[i] = e; ssum += e;
            }
            #pragma unroll
            for (int o = 16; o > 0; o >>= 1) ssum += __shfl_xor_sync(0xffffffffu, ssum, o);
            float inv = 1.0f / ssum;
            for (int i = lane; i < cnt; i += 32){
                float wgt = row[i] * inv; row[i] = wgt; swp[q*256 + i] = pack2(wgt, wgt);
            }
        }
        // dense zeros for attn_weights rows
        float* owbase = out_w + orow*Kn;
        #pragma unroll
        for (int i = 0; i < 2; i++)
            ((float4*)owbase)[tid + i*256] = make_float4(0.f,0.f,0.f,0.f);
        __syncthreads();
        // scatter active weights
        for (int e = tid; e < 8*256; e += 256){
            int q = e >> 8, i = e & 255;
            if (i < cnt) owbase[(size_t)q*Kn + sidx[i]] = sw[q*256 + i];
        }
    } else {
        // all-masked: uniform weights, attn over all value rows
        const float wu = 1.0f / (float)Kn;
        for (int i = tid; i < Kn; i += 256) sidx[i] = i;
        for (int e = tid; e < 8*256; e += 256){ sw[e] = wu; swp[e] = pack2(wu, wu); }
        float* owbase = out_w + orow*Kn;
        #pragma unroll
        for (int i = 0; i < 2; i++)
            ((float4*)owbase)[tid + i*256] = make_float4(wu,wu,wu,wu);
        cnt = Kn;
        __syncthreads();
    }

    // phase 3: attn_vec, thread covers v cols (2*tid, 2*tid+1) for all 8 q.
    // unroll 8 for deeper MLP (value rows are L2-resident, ~250cyc).
    u64 acc2[8];
    #pragma unroll
    for (int q = 0; q < 8; q++) acc2[q] = 0ull;
    const float* vb = value + (size_t)b*Kn*Vv + 2*tid;
    #pragma unroll 8
    for (int i = 0; i < cnt; i++){
        u64 vv = *(const u64*)(vb + (size_t)sidx[i]*Vv);
        #pragma unroll
        for (int q = 0; q < 8; q++) fma2(acc2[q], swp[q*256 + i], vv);
    }
    float* ovbase = out_v + orow*Vv + 2*tid;
    #pragma unroll
    for (int q = 0; q < 8; q++){
        float lo, hi; unpack2(acc2[q], lo, hi);
        *(float2*)(ovbase + (size_t)q*Vv) = make_float2(lo, hi);
    }
}

// ---------------------------------------------------------------------------
extern "C" void kernel_launch(void* const* d_in, const int* in_sizes, int n_in,
                              void* d_out, int out_size){
    const float* query = (const float*)d_in[0];
    const float* key_  = (const float*)d_in[1];
    const float* value = (const float*)d_in[2];
    const int*   mask  = (const int*)  d_in[3];
    const float* W1    = (const float*)d_in[4];
    const float* b1    = (const float*)d_in[5];
    const float* w2    = (const float*)d_in[6];

    float* out = (float*)d_out;
    float* out_vec = out;                       // (B,Q,V)
    float* out_w   = out + (size_t)Bb*Qn*Vv;    // (B,Q,K)

    cudaFuncSetAttribute(fused_kernel,
                         cudaFuncAttributeMaxDynamicSharedMemorySize, FUSED_SMEM);

    dim3 gp(Hh/64, (Bb*Qn + Bb*Kn)/64);         // (8, 48); key tiles may exit
    proj_kernel<<<gp, 256>>>(query, key_, W1, b1, mask);

    dim3 gf(Qn/8, Bb);                          // (16, 8) = 128 blocks
    fused_kernel<<<gf, 256, FUSED_SMEM>>>(value, w2, out_w, out_vec);
}